// round 10
// baseline (speedup 1.0000x reference)
#include <cuda_runtime.h>
#include <math.h>

// Problem constants
#define BB   16
#define SS   512
#define NCH  321
#define DD   512
#define DFF  2048
#define PP   96
#define BN   (BB*NCH)          // 5136 tokens

// ---------------------------------------------------------------------------
// Scratch buffers (device globals; no runtime allocation allowed)
// ---------------------------------------------------------------------------
__device__ float g_means[BN];
__device__ float g_stdev[BN];
__device__ float g_xn    [(size_t)BN*SS];
__device__ float g_h     [(size_t)BN*DD];
__device__ float g_coeffs[(size_t)BN*4*DD];
__device__ float g_q     [(size_t)BN*4*DD];
__device__ float g_k     [(size_t)BN*4*DD];
__device__ float g_v     [(size_t)BN*4*DD];
__device__ float g_qn2   [BB*4*DD];
__device__ float g_kn2   [BB*4*DD];
__device__ float g_sc    [(size_t)BB*4*DD*DD];   // 64 x 512 x 512
__device__ float g_attn  [(size_t)BN*4*DD];
__device__ float g_rec   [(size_t)BN*DD];
__device__ float g_o     [(size_t)BN*DD];
__device__ float g_x1    [(size_t)BN*DD];
__device__ float g_y     [(size_t)BN*DFF];
__device__ float g_z     [(size_t)BN*DD];
__device__ float g_hf    [(size_t)BN*DD];
__device__ float g_dec   [(size_t)BN*PP];

// ---------------------------------------------------------------------------
// Block reduction helpers (blockDim.x == 256)
// ---------------------------------------------------------------------------
__device__ __forceinline__ float blk_sum(float v, float* sh) {
    #pragma unroll
    for (int o = 16; o; o >>= 1) v += __shfl_xor_sync(0xffffffffu, v, o);
    int t = threadIdx.x;
    if ((t & 31) == 0) sh[t >> 5] = v;
    __syncthreads();
    v = sh[0] + sh[1] + sh[2] + sh[3] + sh[4] + sh[5] + sh[6] + sh[7];
    __syncthreads();
    return v;
}
__device__ __forceinline__ float blk_max(float v, float* sh) {
    #pragma unroll
    for (int o = 16; o; o >>= 1) v = fmaxf(v, __shfl_xor_sync(0xffffffffu, v, o));
    int t = threadIdx.x;
    if ((t & 31) == 0) sh[t >> 5] = v;
    __syncthreads();
    v = fmaxf(fmaxf(fmaxf(sh[0], sh[1]), fmaxf(sh[2], sh[3])),
              fmaxf(fmaxf(sh[4], sh[5]), fmaxf(sh[6], sh[7])));
    __syncthreads();
    return v;
}

// ---------------------------------------------------------------------------
// Generic 128x128x8 SGEMM tile body.
// LAYOUT 0 (NT): C[m,n] = sum_k A[m*lda+k] * B[n*ldb+k]    (K contiguous)
//                -> requires K % 8 == 0 and 16B-aligned rows (true at all call
//                   sites: K in {512, 2048}, lda/ldb in {512, 2048}).
// LAYOUT 1 (TN): C[m,n] = sum_k A[k*lda+m] * B[k*ldb+n]    (arbitrary K)
// EPI 0: +bias          EPI 1: +bias then exact GELU
// EPI 2: geometric attention score:
//        s = (0.7*dot + 0.3*sqrt(max(rown[m]*coln[n]-dot^2,0)+1e-8)) / sqrt(321)
// ---------------------------------------------------------------------------
template<int LAYOUT, int EPI>
__device__ __forceinline__ void gemm_tile(
    const float* __restrict__ A, const float* __restrict__ Bm,
    const float* __restrict__ bias, float* __restrict__ C,
    int M, int N, int K, int lda, int ldb, int ldc,
    const float* __restrict__ rown, const float* __restrict__ coln)
{
    __shared__ float As[8][128];
    __shared__ float Bs[8][128];
    const int tid = threadIdx.x;
    const int m0 = blockIdx.y * 128;
    const int n0 = blockIdx.x * 128;
    const int tx = tid & 15;
    const int ty = tid >> 4;
    float acc[8][8];
    #pragma unroll
    for (int i = 0; i < 8; i++)
        #pragma unroll
        for (int j = 0; j < 8; j++) acc[i][j] = 0.f;

    for (int k0 = 0; k0 < K; k0 += 8) {
        if (LAYOUT == 0) {
            const int row = tid >> 1;
            const int kc  = (tid & 1) * 4;
            float4 va = make_float4(0.f, 0.f, 0.f, 0.f);
            float4 vb = make_float4(0.f, 0.f, 0.f, 0.f);
            if (m0 + row < M) va = *(const float4*)(A  + (size_t)(m0 + row) * lda + k0 + kc);
            if (n0 + row < N) vb = *(const float4*)(Bm + (size_t)(n0 + row) * ldb + k0 + kc);
            As[kc+0][row] = va.x; As[kc+1][row] = va.y; As[kc+2][row] = va.z; As[kc+3][row] = va.w;
            Bs[kc+0][row] = vb.x; Bs[kc+1][row] = vb.y; Bs[kc+2][row] = vb.z; Bs[kc+3][row] = vb.w;
        } else {
            const int col = tid & 127;
            const int kb  = tid >> 7;
            #pragma unroll
            for (int r = 0; r < 8; r += 2) {
                const int kk = kb + r;
                const int gk = k0 + kk;
                float av = 0.f, bv = 0.f;
                if (gk < K) {
                    if (m0 + col < M) av = A [(size_t)gk * lda + m0 + col];
                    if (n0 + col < N) bv = Bm[(size_t)gk * ldb + n0 + col];
                }
                As[kk][col] = av;
                Bs[kk][col] = bv;
            }
        }
        __syncthreads();
        #pragma unroll
        for (int kk = 0; kk < 8; kk++) {
            const float4* a4 = (const float4*)(&As[kk][ty * 8]);
            const float4* b4 = (const float4*)(&Bs[kk][tx * 8]);
            float4 a0 = a4[0], a1 = a4[1];
            float4 b0 = b4[0], b1 = b4[1];
            float a[8] = {a0.x, a0.y, a0.z, a0.w, a1.x, a1.y, a1.z, a1.w};
            float b[8] = {b0.x, b0.y, b0.z, b0.w, b1.x, b1.y, b1.z, b1.w};
            #pragma unroll
            for (int i = 0; i < 8; i++)
                #pragma unroll
                for (int j = 0; j < 8; j++)
                    acc[i][j] = fmaf(a[i], b[j], acc[i][j]);
        }
        __syncthreads();
    }

    const float scale = rsqrtf(321.0f);
    #pragma unroll
    for (int i = 0; i < 8; i++) {
        const int gm = m0 + ty * 8 + i;
        if (gm >= M) continue;
        #pragma unroll
        for (int j = 0; j < 8; j++) {
            const int gn = n0 + tx * 8 + j;
            if (gn >= N) continue;
            float vv = acc[i][j];
            if (EPI == 0 || EPI == 1) { if (bias) vv += bias[gn]; }
            if (EPI == 1) vv = 0.5f * vv * (1.f + erff(vv * 0.70710678118654752f));
            if (EPI == 2) {
                float w = rown[gm] * coln[gn] - vv * vv;
                w = sqrtf(fmaxf(w, 0.f) + 1e-8f);
                vv = (0.7f * vv + 0.3f * w) * scale;
            }
            C[(size_t)gm * ldc + gn] = vv;
        }
    }
}

__global__ void __launch_bounds__(256) k_gemm(
    const float* __restrict__ A, const float* __restrict__ B,
    const float* __restrict__ bias, float* __restrict__ C, int M, int N, int K)
{
    gemm_tile<0, 0>(A, B, bias, C, M, N, K, K, K, N, nullptr, nullptr);
}
__global__ void __launch_bounds__(256) k_gemm_gelu(
    const float* __restrict__ A, const float* __restrict__ B,
    const float* __restrict__ bias, float* __restrict__ C, int M, int N, int K)
{
    gemm_tile<0, 1>(A, B, bias, C, M, N, K, K, K, N, nullptr, nullptr);
}

// dot + geometric score, batched over z = b*4 + head
// Q^T, K^T are views: q_lin[((b*NCH+j)*4+m)*512 + l]  (row j stride 2048)
__global__ void __launch_bounds__(256) k_dot_geom(
    const float* __restrict__ q, const float* __restrict__ k,
    const float* __restrict__ qn2, const float* __restrict__ kn2,
    float* __restrict__ sc)
{
    const int z = blockIdx.z;
    const int b = z >> 2, m = z & 3;
    const float* A  = q + (size_t)b * NCH * 2048 + m * 512;
    const float* Bm = k + (size_t)b * NCH * 2048 + m * 512;
    float* C = sc + (size_t)z * DD * DD;
    gemm_tile<1, 2>(A, Bm, nullptr, C, DD, DD, NCH, 2048, 2048, DD,
                    qn2 + z * DD, kn2 + z * DD);
}

// attn out: C[d, l] = sum_s V^T[d,s] * P[l,s], batched over z = b*4 + head
__global__ void __launch_bounds__(256) k_av(
    const float* __restrict__ v, const float* __restrict__ pr,
    float* __restrict__ attn)
{
    const int z = blockIdx.z;
    const int b = z >> 2, m = z & 3;
    const float* A  = v  + (size_t)b * NCH * 2048 + m * 512;
    const float* Bm = pr + (size_t)z * DD * DD;
    float* C = attn + (size_t)b * NCH * 2048 + m * 512;
    gemm_tile<0, 0>(A, Bm, nullptr, C, NCH, DD, DD, 2048, DD, 2048, nullptr, nullptr);
}

// ---------------------------------------------------------------------------
// Input stats: means/stdev over S per (b, n)
// ---------------------------------------------------------------------------
__global__ void k_stats(const float* __restrict__ x,
                        float* __restrict__ means, float* __restrict__ stdev)
{
    const int b = blockIdx.x;
    const int n = blockIdx.y * 32 + threadIdx.x;
    float s = 0.f, s2 = 0.f;
    if (n < NCH) {
        for (int t = threadIdx.y; t < SS; t += 8) {
            float vv = x[((size_t)b * SS + t) * NCH + n];
            s += vv; s2 = fmaf(vv, vv, s2);
        }
    }
    __shared__ float sh[8][32], sh2[8][32];
    sh [threadIdx.y][threadIdx.x] = s;
    sh2[threadIdx.y][threadIdx.x] = s2;
    __syncthreads();
    if (threadIdx.y == 0 && n < NCH) {
        float a = 0.f, a2 = 0.f;
        #pragma unroll
        for (int i = 0; i < 8; i++) { a += sh[i][threadIdx.x]; a2 += sh2[i][threadIdx.x]; }
        float mu  = a * (1.f / SS);
        float var = a2 * (1.f / SS) - mu * mu;
        means[b * NCH + n] = mu;
        stdev[b * NCH + n] = sqrtf(var + 1e-5f);
    }
}

// Normalize + transpose: xn[b, n, s] = (x[b, s, n] - mu) / sd
__global__ void k_normT(const float* __restrict__ x,
                        const float* __restrict__ means, const float* __restrict__ stdev,
                        float* __restrict__ xn)
{
    __shared__ float tile[32][33];
    const int b  = blockIdx.z;
    const int s0 = blockIdx.x * 32;
    const int n0 = blockIdx.y * 32;
    #pragma unroll
    for (int r = 0; r < 4; r++) {
        int ss = s0 + threadIdx.y + r * 8;
        int nn = n0 + threadIdx.x;
        tile[threadIdx.y + r * 8][threadIdx.x] =
            (nn < NCH) ? x[((size_t)b * SS + ss) * NCH + nn] : 0.f;
    }
    __syncthreads();
    #pragma unroll
    for (int r = 0; r < 4; r++) {
        int nn = n0 + threadIdx.y + r * 8;
        int ss = s0 + threadIdx.x;
        if (nn < NCH) {
            float mu = means[b * NCH + nn];
            float sd = stdev[b * NCH + nn];
            xn[((size_t)b * NCH + nn) * SS + ss] =
                (tile[threadIdx.x][threadIdx.y + r * 8] - mu) / sd;
        }
    }
}

// ---------------------------------------------------------------------------
// SWT decomposition along D (per (b,n) row, wrap padding, 3 levels, K=3 taps)
// coeffs[bn][0]=final approx, [1]=det dil4, [2]=det dil2, [3]=det dil1
// ---------------------------------------------------------------------------
__global__ void __launch_bounds__(512) k_swt_dec(
    const float* __restrict__ h, const float* __restrict__ h0,
    const float* __restrict__ h1, float* __restrict__ coeffs)
{
    const int bn = blockIdx.x;
    const int n  = bn % NCH;
    const int d  = threadIdx.x;
    __shared__ float buf[2][DD];
    buf[0][d] = h[(size_t)bn * DD + d];
    float f0[3], f1[3];
    #pragma unroll
    for (int kk = 0; kk < 3; kk++) { f0[kk] = h0[n * 3 + kk]; f1[kk] = h1[n * 3 + kk]; }
    __syncthreads();
    int cur = 0, dil = 1;
    const int pl[3] = {1, 1, 2};          // 2*dil - (3*dil)/2
    #pragma unroll
    for (int m = 0; m < 3; m++) {
        float det = 0.f, app = 0.f;
        #pragma unroll
        for (int kk = 0; kk < 3; kk++) {
            int idx = (d + kk * dil - pl[m] + DD) & (DD - 1);
            float vv = buf[cur][idx];
            det = fmaf(f1[kk], vv, det);
            app = fmaf(f0[kk], vv, app);
        }
        coeffs[((size_t)bn * 4 + (3 - m)) * DD + d] = det;
        buf[cur ^ 1][d] = app;
        __syncthreads();
        cur ^= 1; dil <<= 1;
    }
    coeffs[(size_t)bn * 4 * DD + d] = buf[cur][d];
}

// SWT reconstruction (inverse cascade)
__global__ void __launch_bounds__(512) k_swt_rec(
    const float* __restrict__ c, const float* __restrict__ g0,
    const float* __restrict__ g1, float* __restrict__ rec)
{
    const int bn = blockIdx.x;
    const int n  = bn % NCH;
    const int d  = threadIdx.x;
    __shared__ float app[2][DD];
    __shared__ float det[DD];
    app[0][d] = c[(size_t)bn * 4 * DD + d];
    float f0[3], f1[3];
    #pragma unroll
    for (int kk = 0; kk < 3; kk++) { f0[kk] = g0[n * 3 + kk]; f1[kk] = g1[n * 3 + kk]; }
    int cur = 0, dil = 4;
    const int pl[3] = {6, 3, 1};          // (3*dil)/2
    #pragma unroll
    for (int i = 0; i < 3; i++) {
        det[d] = c[((size_t)bn * 4 + 1 + i) * DD + d];
        __syncthreads();
        float acc = 0.f;
        #pragma unroll
        for (int kk = 0; kk < 3; kk++) {
            int idx = (d + kk * dil - pl[i] + DD) & (DD - 1);
            acc = fmaf(f0[kk], app[cur][idx], acc);
            acc = fmaf(f1[kk], det[idx], acc);
        }
        app[cur ^ 1][d] = 0.5f * acc;
        __syncthreads();
        cur ^= 1; dil >>= 1;
    }
    rec[(size_t)bn * DD + d] = app[cur][d];
}

// Row norms of Q and K over head dim j (NCH), per (b, head, l)
__global__ void __launch_bounds__(256) k_qknorms(
    const float* __restrict__ q, const float* __restrict__ k,
    float* __restrict__ qn2, float* __restrict__ kn2)
{
    const int z = blockIdx.y;
    const int b = z >> 2, m = z & 3;
    const int l = blockIdx.x * 256 + threadIdx.x;
    const size_t base = (size_t)b * NCH * 2048 + m * 512 + l;
    float sq = 0.f, sk = 0.f;
    for (int j = 0; j < NCH; j++) {
        float a = q[base + (size_t)j * 2048]; sq = fmaf(a, a, sq);
        float c = k[base + (size_t)j * 2048]; sk = fmaf(c, c, sk);
    }
    qn2[z * DD + l] = sq;
    kn2[z * DD + l] = sk;
}

// Softmax over 512 columns, one row per block
__global__ void __launch_bounds__(256) k_softmax512(float* __restrict__ sc)
{
    float* row = sc + (size_t)blockIdx.x * DD;
    const int t = threadIdx.x;
    __shared__ float sh[8];
    float v0 = row[t], v1 = row[t + 256];
    float mx = blk_max(fmaxf(v0, v1), sh);
    float e0 = expf(v0 - mx), e1 = expf(v1 - mx);
    float s = blk_sum(e0 + e1, sh);
    float inv = 1.f / s;
    row[t]       = e0 * inv;
    row[t + 256] = e1 * inv;
}

// LayerNorm over D=512 (optionally fused residual add)
__global__ void __launch_bounds__(256) k_ln(
    const float* __restrict__ x, const float* __restrict__ res,
    const float* __restrict__ g, const float* __restrict__ bt,
    float* __restrict__ out)
{
    const size_t base = (size_t)blockIdx.x * DD;
    const int t = threadIdx.x;
    __shared__ float sh[8];
    float v0 = x[base + t], v1 = x[base + t + 256];
    if (res) { v0 += res[base + t]; v1 += res[base + t + 256]; }
    float s = blk_sum(v0 + v1, sh);
    float mu = s * (1.f / DD);
    float d0 = v0 - mu, d1 = v1 - mu;
    float vs = blk_sum(d0 * d0 + d1 * d1, sh);
    float rs = rsqrtf(vs * (1.f / DD) + 1e-5f);
    out[base + t]       = d0 * rs * g[t]       + bt[t];
    out[base + t + 256] = d1 * rs * g[t + 256] + bt[t + 256];
}

// dec output: out[b, p, n] = dec[b, n, p] * stdev[b, n] + means[b, n]
__global__ void k_dec_out(const float* __restrict__ dec,
                          const float* __restrict__ means, const float* __restrict__ stdev,
                          float* __restrict__ out)
{
    const int idx = blockIdx.x * 256 + threadIdx.x;
    if (idx >= BB * PP * NCH) return;
    const int n = idx % NCH;
    const int p = (idx / NCH) % PP;
    const int b = idx / (NCH * PP);
    out[idx] = dec[((size_t)b * NCH + n) * PP + p] * stdev[b * NCH + n] + means[b * NCH + n];
}

__global__ void k_tail(const float* __restrict__ means, const float* __restrict__ stdev,
                       float* __restrict__ out)
{
    const int i = blockIdx.x * 256 + threadIdx.x;
    if (i < BN) { out[i] = means[i]; out[BN + i] = stdev[i]; }
}

// ---------------------------------------------------------------------------
// Launch
// ---------------------------------------------------------------------------
extern "C" void kernel_launch(void* const* d_in, const int* in_sizes, int n_in,
                              void* d_out, int out_size)
{
    const float* x_enc  = (const float*)d_in[0];
    const float* emb_W  = (const float*)d_in[1];
    const float* emb_b  = (const float*)d_in[2];
    const float* h0     = (const float*)d_in[3];
    const float* h1     = (const float*)d_in[4];
    const float* g0     = (const float*)d_in[5];
    const float* g1     = (const float*)d_in[6];
    const float* Wq     = (const float*)d_in[7];
    const float* bq     = (const float*)d_in[8];
    const float* Wk     = (const float*)d_in[9];
    const float* bk     = (const float*)d_in[10];
    const float* Wv     = (const float*)d_in[11];
    const float* bv     = (const float*)d_in[12];
    const float* Wo     = (const float*)d_in[13];
    const float* bo     = (const float*)d_in[14];
    const float* W1     = (const float*)d_in[15];
    const float* b1     = (const float*)d_in[16];
    const float* W2     = (const float*)d_in[17];
    const float* b2     = (const float*)d_in[18];
    const float* ln1_g  = (const float*)d_in[19];
    const float* ln1_b  = (const float*)d_in[20];
    const float* ln2_g  = (const float*)d_in[21];
    const float* ln2_b  = (const float*)d_in[22];
    const float* lnf_g  = (const float*)d_in[23];
    const float* lnf_b  = (const float*)d_in[24];
    const float* proj_W = (const float*)d_in[25];
    const float* proj_b = (const float*)d_in[26];

    float *means, *stdev, *xn, *h, *coeffs, *q, *k, *v, *qn2, *kn2, *sc,
          *attn, *rec, *o, *x1, *y, *z, *hf, *dec;
    cudaGetSymbolAddress((void**)&means,  g_means);
    cudaGetSymbolAddress((void**)&stdev,  g_stdev);
    cudaGetSymbolAddress((void**)&xn,     g_xn);
    cudaGetSymbolAddress((void**)&h,      g_h);
    cudaGetSymbolAddress((void**)&coeffs, g_coeffs);
    cudaGetSymbolAddress((void**)&q,      g_q);
    cudaGetSymbolAddress((void**)&k,      g_k);
    cudaGetSymbolAddress((void**)&v,      g_v);
    cudaGetSymbolAddress((void**)&qn2,    g_qn2);
    cudaGetSymbolAddress((void**)&kn2,    g_kn2);
    cudaGetSymbolAddress((void**)&sc,     g_sc);
    cudaGetSymbolAddress((void**)&attn,   g_attn);
    cudaGetSymbolAddress((void**)&rec,    g_rec);
    cudaGetSymbolAddress((void**)&o,      g_o);
    cudaGetSymbolAddress((void**)&x1,     g_x1);
    cudaGetSymbolAddress((void**)&y,      g_y);
    cudaGetSymbolAddress((void**)&z,      g_z);
    cudaGetSymbolAddress((void**)&hf,     g_hf);
    cudaGetSymbolAddress((void**)&dec,    g_dec);

    // Input stats + normalized transpose
    k_stats<<<dim3(BB, (NCH + 31) / 32), dim3(32, 8)>>>(x_enc, means, stdev);
    k_normT<<<dim3(SS / 32, (NCH + 31) / 32, BB), dim3(32, 8)>>>(x_enc, means, stdev, xn);

    // Embedding: h[bn, d] = xn[bn, :] . emb_W[d, :]
    k_gemm<<<dim3(DD / 128, (BN + 127) / 128), 256>>>(xn, emb_W, emb_b, h, BN, DD, SS);

    const dim3 gQKV(DD / 128, (BN * 4 + 127) / 128);
    const dim3 gD  (DD / 128, (BN + 127) / 128);

    for (int l = 0; l < 2; l++) {
        const float* h0l = h0 + (size_t)l * NCH * 3;
        const float* h1l = h1 + (size_t)l * NCH * 3;
        const float* g0l = g0 + (size_t)l * NCH * 3;
        const float* g1l = g1 + (size_t)l * NCH * 3;

        k_swt_dec<<<BN, DD>>>(h, h0l, h1l, coeffs);

        k_gemm<<<gQKV, 256>>>(coeffs, Wq + (size_t)l * DD * DD, bq + l * DD, q, BN * 4, DD, DD);
        k_gemm<<<gQKV, 256>>>(coeffs, Wk + (size_t)l * DD * DD, bk + l * DD, k, BN * 4, DD, DD);
        k_gemm<<<gQKV, 256>>>(coeffs, Wv + (size_t)l * DD * DD, bv + l * DD, v, BN * 4, DD, DD);

        k_qknorms<<<dim3(2, BB * 4), 256>>>(q, k, qn2, kn2);
        k_dot_geom<<<dim3(4, 4, BB * 4), 256>>>(q, k, qn2, kn2, sc);
        k_softmax512<<<BB * 4 * DD, 256>>>(sc);
        k_av<<<dim3(4, (NCH + 127) / 128, BB * 4), 256>>>(v, sc, attn);

        k_swt_rec<<<BN, DD>>>(attn, g0l, g1l, rec);

        k_gemm<<<gD, 256>>>(rec, Wo + (size_t)l * DD * DD, bo + l * DD, o, BN, DD, DD);
        k_ln<<<BN, 256>>>(h, o, ln1_g + l * DD, ln1_b + l * DD, x1);

        k_gemm_gelu<<<dim3(DFF / 128, (BN + 127) / 128), 256>>>(
            x1, W1 + (size_t)l * DFF * DD, b1 + l * DFF, y, BN, DFF, DD);
        k_gemm<<<gD, 256>>>(y, W2 + (size_t)l * DD * DFF, b2 + l * DD, z, BN, DD, DFF);
        k_ln<<<BN, 256>>>(x1, z, ln2_g + l * DD, ln2_b + l * DD, h);
    }

    // Final LN + projection + de-normalization
    k_ln<<<BN, 256>>>(h, nullptr, lnf_g, lnf_b, hf);
    k_gemm<<<dim3((PP + 127) / 128, (BN + 127) / 128), 256>>>(hf, proj_W, proj_b, dec, BN, PP, DD);
    k_dec_out<<<(BB * PP * NCH + 255) / 256, 256>>>(dec, means, stdev, (float*)d_out);

    // Tuple tail: (dec, means, stdev) flattened
    if (out_size >= BB * PP * NCH + 2 * BN)
        k_tail<<<(BN + 255) / 256, 256>>>(means, stdev, (float*)d_out + BB * PP * NCH);
}

// round 11
// speedup vs baseline: 1.3053x; 1.3053x over previous
#include <cuda_runtime.h>
#include <math.h>

// Problem constants
#define BB   16
#define SS   512
#define NCH  321
#define DD   512
#define DFF  2048
#define PP   96
#define BN   (BB*NCH)          // 5136 tokens

// ---------------------------------------------------------------------------
// Scratch buffers (device globals; no runtime allocation allowed)
// ---------------------------------------------------------------------------
__device__ float g_means[BN];
__device__ float g_stdev[BN];
__device__ float g_xn    [(size_t)BN*SS];
__device__ float g_h     [(size_t)BN*DD];
__device__ float g_coeffs[(size_t)BN*4*DD];
__device__ float g_q     [(size_t)BN*4*DD];
__device__ float g_k     [(size_t)BN*4*DD];
__device__ float g_v     [(size_t)BN*4*DD];
__device__ float g_qn2   [BB*4*DD];
__device__ float g_kn2   [BB*4*DD];
__device__ float g_sc    [(size_t)BB*4*DD*DD];   // 64 x 512 x 512
__device__ float g_attn  [(size_t)BN*4*DD];
__device__ float g_rec   [(size_t)BN*DD];
__device__ float g_o     [(size_t)BN*DD];
__device__ float g_x1    [(size_t)BN*DD];
__device__ float g_y     [(size_t)BN*DFF];
__device__ float g_z     [(size_t)BN*DD];
__device__ float g_hf    [(size_t)BN*DD];
__device__ float g_dec   [(size_t)BN*PP];

// ---------------------------------------------------------------------------
// Block reduction helpers (blockDim.x == 256)
// ---------------------------------------------------------------------------
__device__ __forceinline__ float blk_sum(float v, float* sh) {
    #pragma unroll
    for (int o = 16; o; o >>= 1) v += __shfl_xor_sync(0xffffffffu, v, o);
    int t = threadIdx.x;
    if ((t & 31) == 0) sh[t >> 5] = v;
    __syncthreads();
    v = sh[0] + sh[1] + sh[2] + sh[3] + sh[4] + sh[5] + sh[6] + sh[7];
    __syncthreads();
    return v;
}
__device__ __forceinline__ float blk_max(float v, float* sh) {
    #pragma unroll
    for (int o = 16; o; o >>= 1) v = fmaxf(v, __shfl_xor_sync(0xffffffffu, v, o));
    int t = threadIdx.x;
    if ((t & 31) == 0) sh[t >> 5] = v;
    __syncthreads();
    v = fmaxf(fmaxf(fmaxf(sh[0], sh[1]), fmaxf(sh[2], sh[3])),
              fmaxf(fmaxf(sh[4], sh[5]), fmaxf(sh[6], sh[7])));
    __syncthreads();
    return v;
}

// ---------------------------------------------------------------------------
// 128x128x8 SGEMM tile body, 2-stage smem double buffering with register
// staging (one __syncthreads per k-tile; global-load latency hidden behind
// the 512 FFMA of the current tile).
// LAYOUT 0 (NT): C[m,n] = sum_k A[m*lda+k] * B[n*ldb+k]   (K%8==0, 16B rows)
// LAYOUT 1 (TN): C[m,n] = sum_k A[k*lda+m] * B[k*ldb+n]   (arbitrary K)
// EPI 0: +bias        EPI 1: +bias then exact GELU
// EPI 2: geometric attention score
// ---------------------------------------------------------------------------
template<int LAYOUT, int EPI>
__device__ __forceinline__ void gemm_tile(
    const float* __restrict__ A, const float* __restrict__ Bm,
    const float* __restrict__ bias, float* __restrict__ C,
    int M, int N, int K, int lda, int ldb, int ldc,
    const float* __restrict__ rown, const float* __restrict__ coln)
{
    __shared__ float As[2][8][128];
    __shared__ float Bs[2][8][128];
    const int tid = threadIdx.x;
    const int m0 = blockIdx.y * 128;
    const int n0 = blockIdx.x * 128;
    const int tx = tid & 15;
    const int ty = tid >> 4;
    float acc[8][8];
    #pragma unroll
    for (int i = 0; i < 8; i++)
        #pragma unroll
        for (int j = 0; j < 8; j++) acc[i][j] = 0.f;

    // register staging
    float4 va, vb;                 // LAYOUT 0
    float  av[4], bv[4];           // LAYOUT 1
    const int row = tid >> 1;
    const int kc  = (tid & 1) * 4;
    const int col = tid & 127;
    const int kb  = tid >> 7;      // 0 or 1
    const bool aok = (m0 + ((LAYOUT == 0) ? row : col)) < M;
    const bool bok = (n0 + ((LAYOUT == 0) ? row : col)) < N;

    #define FETCH(k0)                                                          \
        if (LAYOUT == 0) {                                                     \
            va = make_float4(0.f,0.f,0.f,0.f);                                 \
            vb = make_float4(0.f,0.f,0.f,0.f);                                 \
            if (aok) va = *(const float4*)(A  + (size_t)(m0+row)*lda + (k0)+kc);\
            if (bok) vb = *(const float4*)(Bm + (size_t)(n0+row)*ldb + (k0)+kc);\
        } else {                                                               \
            _Pragma("unroll")                                                  \
            for (int r = 0; r < 4; r++) {                                      \
                const int gk = (k0) + kb + 2*r;                                \
                av[r] = 0.f; bv[r] = 0.f;                                      \
                if (gk < K) {                                                  \
                    if (aok) av[r] = A [(size_t)gk*lda + m0+col];              \
                    if (bok) bv[r] = Bm[(size_t)gk*ldb + n0+col];              \
                }                                                              \
            }                                                                  \
        }

    #define STAGE(bf)                                                          \
        if (LAYOUT == 0) {                                                     \
            As[bf][kc+0][row]=va.x; As[bf][kc+1][row]=va.y;                    \
            As[bf][kc+2][row]=va.z; As[bf][kc+3][row]=va.w;                    \
            Bs[bf][kc+0][row]=vb.x; Bs[bf][kc+1][row]=vb.y;                    \
            Bs[bf][kc+2][row]=vb.z; Bs[bf][kc+3][row]=vb.w;                    \
        } else {                                                               \
            _Pragma("unroll")                                                  \
            for (int r = 0; r < 4; r++) {                                      \
                As[bf][kb+2*r][col] = av[r];                                   \
                Bs[bf][kb+2*r][col] = bv[r];                                   \
            }                                                                  \
        }

    #define COMPUTE(bf)                                                        \
        _Pragma("unroll")                                                      \
        for (int kk = 0; kk < 8; kk++) {                                       \
            float a[8], b[8];                                                  \
            *(float4*)(a)   = *(const float4*)(&As[bf][kk][ty*8]);             \
            *(float4*)(a+4) = *(const float4*)(&As[bf][kk][ty*8+4]);           \
            *(float4*)(b)   = *(const float4*)(&Bs[bf][kk][tx*8]);             \
            *(float4*)(b+4) = *(const float4*)(&Bs[bf][kk][tx*8+4]);           \
            _Pragma("unroll")                                                  \
            for (int i = 0; i < 8; i++)                                        \
                _Pragma("unroll")                                              \
                for (int j = 0; j < 8; j++)                                    \
                    acc[i][j] = fmaf(a[i], b[j], acc[i][j]);                   \
        }

    FETCH(0); STAGE(0); __syncthreads();
    int buf = 0;
    for (int k0 = 8; k0 < K; k0 += 8) {
        FETCH(k0);
        COMPUTE(buf);
        STAGE(buf ^ 1);
        __syncthreads();
        buf ^= 1;
    }
    COMPUTE(buf);

    #undef FETCH
    #undef STAGE
    #undef COMPUTE

    const float scale = rsqrtf(321.0f);
    #pragma unroll
    for (int i = 0; i < 8; i++) {
        const int gm = m0 + ty * 8 + i;
        if (gm >= M) continue;
        float outv[8];
        #pragma unroll
        for (int j = 0; j < 8; j++) {
            const int gn = n0 + tx * 8 + j;
            float vv = acc[i][j];
            if (EPI == 0 || EPI == 1) { if (bias && gn < N) vv += bias[gn]; }
            if (EPI == 1) vv = 0.5f * vv * (1.f + erff(vv * 0.70710678118654752f));
            if (EPI == 2) {
                float cn = (gn < N) ? coln[gn] : 0.f;
                float w = rown[gm] * cn - vv * vv;
                w = sqrtf(fmaxf(w, 0.f) + 1e-8f);
                vv = (0.7f * vv + 0.3f * w) * scale;
            }
            outv[j] = vv;
        }
        float* crow = C + (size_t)gm * ldc + n0 + tx * 8;
        if (n0 + tx * 8 + 7 < N && (ldc & 3) == 0) {
            *(float4*)(crow)     = make_float4(outv[0], outv[1], outv[2], outv[3]);
            *(float4*)(crow + 4) = make_float4(outv[4], outv[5], outv[6], outv[7]);
        } else {
            #pragma unroll
            for (int j = 0; j < 8; j++)
                if (n0 + tx * 8 + j < N) crow[j] = outv[j];
        }
    }
}

__global__ void __launch_bounds__(256, 2) k_gemm(
    const float* __restrict__ A, const float* __restrict__ B,
    const float* __restrict__ bias, float* __restrict__ C, int M, int N, int K)
{
    gemm_tile<0, 0>(A, B, bias, C, M, N, K, K, K, N, nullptr, nullptr);
}
__global__ void __launch_bounds__(256, 2) k_gemm_gelu(
    const float* __restrict__ A, const float* __restrict__ B,
    const float* __restrict__ bias, float* __restrict__ C, int M, int N, int K)
{
    gemm_tile<0, 1>(A, B, bias, C, M, N, K, K, K, N, nullptr, nullptr);
}

// Fused Q/K/V projection: blockIdx.z selects which projection this CTA does.
__global__ void __launch_bounds__(256, 2) k_qkv(
    const float* __restrict__ coeffs,
    const float* __restrict__ Wq, const float* __restrict__ Wk, const float* __restrict__ Wv,
    const float* __restrict__ bq, const float* __restrict__ bk, const float* __restrict__ bv,
    float* __restrict__ q, float* __restrict__ k, float* __restrict__ v)
{
    const float* W; const float* bi; float* out;
    if (blockIdx.z == 0)      { W = Wq; bi = bq; out = q; }
    else if (blockIdx.z == 1) { W = Wk; bi = bk; out = k; }
    else                      { W = Wv; bi = bv; out = v; }
    gemm_tile<0, 0>(coeffs, W, bi, out, BN * 4, DD, DD, DD, DD, DD, nullptr, nullptr);
}

// dot + geometric score, batched over z = b*4 + head
__global__ void __launch_bounds__(256, 2) k_dot_geom(
    const float* __restrict__ q, const float* __restrict__ k,
    const float* __restrict__ qn2, const float* __restrict__ kn2,
    float* __restrict__ sc)
{
    const int z = blockIdx.z;
    const int b = z >> 2, m = z & 3;
    const float* A  = q + (size_t)b * NCH * 2048 + m * 512;
    const float* Bm = k + (size_t)b * NCH * 2048 + m * 512;
    float* C = sc + (size_t)z * DD * DD;
    gemm_tile<1, 2>(A, Bm, nullptr, C, DD, DD, NCH, 2048, 2048, DD,
                    qn2 + z * DD, kn2 + z * DD);
}

// attn out: C[d, l] = sum_s V^T[d,s] * P[l,s], batched over z = b*4 + head
__global__ void __launch_bounds__(256, 2) k_av(
    const float* __restrict__ v, const float* __restrict__ pr,
    float* __restrict__ attn)
{
    const int z = blockIdx.z;
    const int b = z >> 2, m = z & 3;
    const float* A  = v  + (size_t)b * NCH * 2048 + m * 512;
    const float* Bm = pr + (size_t)z * DD * DD;
    float* C = attn + (size_t)b * NCH * 2048 + m * 512;
    gemm_tile<0, 0>(A, Bm, nullptr, C, NCH, DD, DD, 2048, DD, 2048, nullptr, nullptr);
}

// ---------------------------------------------------------------------------
// Input stats: means/stdev over S per (b, n)
// ---------------------------------------------------------------------------
__global__ void k_stats(const float* __restrict__ x,
                        float* __restrict__ means, float* __restrict__ stdev)
{
    const int b = blockIdx.x;
    const int n = blockIdx.y * 32 + threadIdx.x;
    float s = 0.f, s2 = 0.f;
    if (n < NCH) {
        for (int t = threadIdx.y; t < SS; t += 8) {
            float vv = x[((size_t)b * SS + t) * NCH + n];
            s += vv; s2 = fmaf(vv, vv, s2);
        }
    }
    __shared__ float sh[8][32], sh2[8][32];
    sh [threadIdx.y][threadIdx.x] = s;
    sh2[threadIdx.y][threadIdx.x] = s2;
    __syncthreads();
    if (threadIdx.y == 0 && n < NCH) {
        float a = 0.f, a2 = 0.f;
        #pragma unroll
        for (int i = 0; i < 8; i++) { a += sh[i][threadIdx.x]; a2 += sh2[i][threadIdx.x]; }
        float mu  = a * (1.f / SS);
        float var = a2 * (1.f / SS) - mu * mu;
        means[b * NCH + n] = mu;
        stdev[b * NCH + n] = sqrtf(var + 1e-5f);
    }
}

// Normalize + transpose: xn[b, n, s] = (x[b, s, n] - mu) / sd
__global__ void k_normT(const float* __restrict__ x,
                        const float* __restrict__ means, const float* __restrict__ stdev,
                        float* __restrict__ xn)
{
    __shared__ float tile[32][33];
    const int b  = blockIdx.z;
    const int s0 = blockIdx.x * 32;
    const int n0 = blockIdx.y * 32;
    #pragma unroll
    for (int r = 0; r < 4; r++) {
        int ss = s0 + threadIdx.y + r * 8;
        int nn = n0 + threadIdx.x;
        tile[threadIdx.y + r * 8][threadIdx.x] =
            (nn < NCH) ? x[((size_t)b * SS + ss) * NCH + nn] : 0.f;
    }
    __syncthreads();
    #pragma unroll
    for (int r = 0; r < 4; r++) {
        int nn = n0 + threadIdx.y + r * 8;
        int ss = s0 + threadIdx.x;
        if (nn < NCH) {
            float mu = means[b * NCH + nn];
            float sd = stdev[b * NCH + nn];
            xn[((size_t)b * NCH + nn) * SS + ss] =
                (tile[threadIdx.x][threadIdx.y + r * 8] - mu) / sd;
        }
    }
}

// ---------------------------------------------------------------------------
// SWT decomposition along D (per (b,n) row, wrap padding, 3 levels, K=3 taps)
// ---------------------------------------------------------------------------
__global__ void __launch_bounds__(512) k_swt_dec(
    const float* __restrict__ h, const float* __restrict__ h0,
    const float* __restrict__ h1, float* __restrict__ coeffs)
{
    const int bn = blockIdx.x;
    const int n  = bn % NCH;
    const int d  = threadIdx.x;
    __shared__ float buf[2][DD];
    buf[0][d] = h[(size_t)bn * DD + d];
    float f0[3], f1[3];
    #pragma unroll
    for (int kk = 0; kk < 3; kk++) { f0[kk] = h0[n * 3 + kk]; f1[kk] = h1[n * 3 + kk]; }
    __syncthreads();
    int cur = 0, dil = 1;
    const int pl[3] = {1, 1, 2};
    #pragma unroll
    for (int m = 0; m < 3; m++) {
        float det = 0.f, app = 0.f;
        #pragma unroll
        for (int kk = 0; kk < 3; kk++) {
            int idx = (d + kk * dil - pl[m] + DD) & (DD - 1);
            float vv = buf[cur][idx];
            det = fmaf(f1[kk], vv, det);
            app = fmaf(f0[kk], vv, app);
        }
        coeffs[((size_t)bn * 4 + (3 - m)) * DD + d] = det;
        buf[cur ^ 1][d] = app;
        __syncthreads();
        cur ^= 1; dil <<= 1;
    }
    coeffs[(size_t)bn * 4 * DD + d] = buf[cur][d];
}

// SWT reconstruction (inverse cascade)
__global__ void __launch_bounds__(512) k_swt_rec(
    const float* __restrict__ c, const float* __restrict__ g0,
    const float* __restrict__ g1, float* __restrict__ rec)
{
    const int bn = blockIdx.x;
    const int n  = bn % NCH;
    const int d  = threadIdx.x;
    __shared__ float app[2][DD];
    __shared__ float det[DD];
    app[0][d] = c[(size_t)bn * 4 * DD + d];
    float f0[3], f1[3];
    #pragma unroll
    for (int kk = 0; kk < 3; kk++) { f0[kk] = g0[n * 3 + kk]; f1[kk] = g1[n * 3 + kk]; }
    int cur = 0, dil = 4;
    const int pl[3] = {6, 3, 1};
    #pragma unroll
    for (int i = 0; i < 3; i++) {
        det[d] = c[((size_t)bn * 4 + 1 + i) * DD + d];
        __syncthreads();
        float acc = 0.f;
        #pragma unroll
        for (int kk = 0; kk < 3; kk++) {
            int idx = (d + kk * dil - pl[i] + DD) & (DD - 1);
            acc = fmaf(f0[kk], app[cur][idx], acc);
            acc = fmaf(f1[kk], det[idx], acc);
        }
        app[cur ^ 1][d] = 0.5f * acc;
        __syncthreads();
        cur ^= 1; dil >>= 1;
    }
    rec[(size_t)bn * DD + d] = app[cur][d];
}

// Row norms of Q and K over head dim j (NCH), per (b, head, l)
__global__ void __launch_bounds__(256) k_qknorms(
    const float* __restrict__ q, const float* __restrict__ k,
    float* __restrict__ qn2, float* __restrict__ kn2)
{
    const int z = blockIdx.y;
    const int b = z >> 2, m = z & 3;
    const int l = blockIdx.x * 256 + threadIdx.x;
    const size_t base = (size_t)b * NCH * 2048 + m * 512 + l;
    float sq = 0.f, sk = 0.f;
    for (int j = 0; j < NCH; j++) {
        float a = q[base + (size_t)j * 2048]; sq = fmaf(a, a, sq);
        float c = k[base + (size_t)j * 2048]; sk = fmaf(c, c, sk);
    }
    qn2[z * DD + l] = sq;
    kn2[z * DD + l] = sk;
}

// Softmax over 512 columns, one row per block
__global__ void __launch_bounds__(256) k_softmax512(float* __restrict__ sc)
{
    float* row = sc + (size_t)blockIdx.x * DD;
    const int t = threadIdx.x;
    __shared__ float sh[8];
    float v0 = row[t], v1 = row[t + 256];
    float mx = blk_max(fmaxf(v0, v1), sh);
    float e0 = expf(v0 - mx), e1 = expf(v1 - mx);
    float s = blk_sum(e0 + e1, sh);
    float inv = 1.f / s;
    row[t]       = e0 * inv;
    row[t + 256] = e1 * inv;
}

// LayerNorm over D=512 (optionally fused residual add)
__global__ void __launch_bounds__(256) k_ln(
    const float* __restrict__ x, const float* __restrict__ res,
    const float* __restrict__ g, const float* __restrict__ bt,
    float* __restrict__ out)
{
    const size_t base = (size_t)blockIdx.x * DD;
    const int t = threadIdx.x;
    __shared__ float sh[8];
    float v0 = x[base + t], v1 = x[base + t + 256];
    if (res) { v0 += res[base + t]; v1 += res[base + t + 256]; }
    float s = blk_sum(v0 + v1, sh);
    float mu = s * (1.f / DD);
    float d0 = v0 - mu, d1 = v1 - mu;
    float vs = blk_sum(d0 * d0 + d1 * d1, sh);
    float rs = rsqrtf(vs * (1.f / DD) + 1e-5f);
    out[base + t]       = d0 * rs * g[t]       + bt[t];
    out[base + t + 256] = d1 * rs * g[t + 256] + bt[t + 256];
}

// dec output: out[b, p, n] = dec[b, n, p] * stdev[b, n] + means[b, n]
__global__ void k_dec_out(const float* __restrict__ dec,
                          const float* __restrict__ means, const float* __restrict__ stdev,
                          float* __restrict__ out)
{
    const int idx = blockIdx.x * 256 + threadIdx.x;
    if (idx >= BB * PP * NCH) return;
    const int n = idx % NCH;
    const int p = (idx / NCH) % PP;
    const int b = idx / (NCH * PP);
    out[idx] = dec[((size_t)b * NCH + n) * PP + p] * stdev[b * NCH + n] + means[b * NCH + n];
}

__global__ void k_tail(const float* __restrict__ means, const float* __restrict__ stdev,
                       float* __restrict__ out)
{
    const int i = blockIdx.x * 256 + threadIdx.x;
    if (i < BN) { out[i] = means[i]; out[BN + i] = stdev[i]; }
}

// ---------------------------------------------------------------------------
// Launch
// ---------------------------------------------------------------------------
extern "C" void kernel_launch(void* const* d_in, const int* in_sizes, int n_in,
                              void* d_out, int out_size)
{
    const float* x_enc  = (const float*)d_in[0];
    const float* emb_W  = (const float*)d_in[1];
    const float* emb_b  = (const float*)d_in[2];
    const float* h0     = (const float*)d_in[3];
    const float* h1     = (const float*)d_in[4];
    const float* g0     = (const float*)d_in[5];
    const float* g1     = (const float*)d_in[6];
    const float* Wq     = (const float*)d_in[7];
    const float* bq     = (const float*)d_in[8];
    const float* Wk     = (const float*)d_in[9];
    const float* bk     = (const float*)d_in[10];
    const float* Wv     = (const float*)d_in[11];
    const float* bv     = (const float*)d_in[12];
    const float* Wo     = (const float*)d_in[13];
    const float* bo     = (const float*)d_in[14];
    const float* W1     = (const float*)d_in[15];
    const float* b1     = (const float*)d_in[16];
    const float* W2     = (const float*)d_in[17];
    const float* b2     = (const float*)d_in[18];
    const float* ln1_g  = (const float*)d_in[19];
    const float* ln1_b  = (const float*)d_in[20];
    const float* ln2_g  = (const float*)d_in[21];
    const float* ln2_b  = (const float*)d_in[22];
    const float* lnf_g  = (const float*)d_in[23];
    const float* lnf_b  = (const float*)d_in[24];
    const float* proj_W = (const float*)d_in[25];
    const float* proj_b = (const float*)d_in[26];

    float *means, *stdev, *xn, *h, *coeffs, *q, *k, *v, *qn2, *kn2, *sc,
          *attn, *rec, *o, *x1, *y, *z, *hf, *dec;
    cudaGetSymbolAddress((void**)&means,  g_means);
    cudaGetSymbolAddress((void**)&stdev,  g_stdev);
    cudaGetSymbolAddress((void**)&xn,     g_xn);
    cudaGetSymbolAddress((void**)&h,      g_h);
    cudaGetSymbolAddress((void**)&coeffs, g_coeffs);
    cudaGetSymbolAddress((void**)&q,      g_q);
    cudaGetSymbolAddress((void**)&k,      g_k);
    cudaGetSymbolAddress((void**)&v,      g_v);
    cudaGetSymbolAddress((void**)&qn2,    g_qn2);
    cudaGetSymbolAddress((void**)&kn2,    g_kn2);
    cudaGetSymbolAddress((void**)&sc,     g_sc);
    cudaGetSymbolAddress((void**)&attn,   g_attn);
    cudaGetSymbolAddress((void**)&rec,    g_rec);
    cudaGetSymbolAddress((void**)&o,      g_o);
    cudaGetSymbolAddress((void**)&x1,     g_x1);
    cudaGetSymbolAddress((void**)&y,      g_y);
    cudaGetSymbolAddress((void**)&z,      g_z);
    cudaGetSymbolAddress((void**)&hf,     g_hf);
    cudaGetSymbolAddress((void**)&dec,    g_dec);

    // Input stats + normalized transpose
    k_stats<<<dim3(BB, (NCH + 31) / 32), dim3(32, 8)>>>(x_enc, means, stdev);
    k_normT<<<dim3(SS / 32, (NCH + 31) / 32, BB), dim3(32, 8)>>>(x_enc, means, stdev, xn);

    // Embedding: h[bn, d] = xn[bn, :] . emb_W[d, :]
    k_gemm<<<dim3(DD / 128, (BN + 127) / 128), 256>>>(xn, emb_W, emb_b, h, BN, DD, SS);

    const dim3 gQKV(DD / 128, (BN * 4 + 127) / 128, 3);
    const dim3 gD  (DD / 128, (BN + 127) / 128);

    for (int l = 0; l < 2; l++) {
        const float* h0l = h0 + (size_t)l * NCH * 3;
        const float* h1l = h1 + (size_t)l * NCH * 3;
        const float* g0l = g0 + (size_t)l * NCH * 3;
        const float* g1l = g1 + (size_t)l * NCH * 3;

        k_swt_dec<<<BN, DD>>>(h, h0l, h1l, coeffs);

        k_qkv<<<gQKV, 256>>>(coeffs,
                             Wq + (size_t)l * DD * DD, Wk + (size_t)l * DD * DD,
                             Wv + (size_t)l * DD * DD,
                             bq + l * DD, bk + l * DD, bv + l * DD, q, k, v);

        k_qknorms<<<dim3(2, BB * 4), 256>>>(q, k, qn2, kn2);
        k_dot_geom<<<dim3(4, 4, BB * 4), 256>>>(q, k, qn2, kn2, sc);
        k_softmax512<<<BB * 4 * DD, 256>>>(sc);
        k_av<<<dim3(4, (NCH + 127) / 128, BB * 4), 256>>>(v, sc, attn);

        k_swt_rec<<<BN, DD>>>(attn, g0l, g1l, rec);

        k_gemm<<<gD, 256>>>(rec, Wo + (size_t)l * DD * DD, bo + l * DD, o, BN, DD, DD);
        k_ln<<<BN, 256>>>(h, o, ln1_g + l * DD, ln1_b + l * DD, x1);

        k_gemm_gelu<<<dim3(DFF / 128, (BN + 127) / 128), 256>>>(
            x1, W1 + (size_t)l * DFF * DD, b1 + l * DFF, y, BN, DFF, DD);
        k_gemm<<<gD, 256>>>(y, W2 + (size_t)l * DD * DFF, b2 + l * DD, z, BN, DD, DFF);
        k_ln<<<BN, 256>>>(x1, z, ln2_g + l * DD, ln2_b + l * DD, h);
    }

    // Final LN + projection + de-normalization
    k_ln<<<BN, 256>>>(h, nullptr, lnf_g, lnf_b, hf);
    k_gemm<<<dim3((PP + 127) / 128, (BN + 127) / 128), 256>>>(hf, proj_W, proj_b, dec, BN, PP, DD);
    k_dec_out<<<(BB * PP * NCH + 255) / 256, 256>>>(dec, means, stdev, (float*)d_out);

    // Tuple tail: (dec, means, stdev) flattened
    if (out_size >= BB * PP * NCH + 2 * BN)
        k_tail<<<(BN + 255) / 256, 256>>>(means, stdev, (float*)d_out + BB * PP * NCH);
}

// round 12
// speedup vs baseline: 1.7742x; 1.3592x over previous
#include <cuda_runtime.h>
#include <math.h>
#include <stdint.h>

// Problem constants
#define BB   16
#define SS   512
#define NCH  321
#define DD   512
#define DFF  2048
#define PP   96
#define BN   (BB*NCH)          // 5136 tokens

// ---------------------------------------------------------------------------
// Scratch buffers
// ---------------------------------------------------------------------------
__device__ float g_means[BN];
__device__ float g_stdev[BN];
__device__ float g_xn    [(size_t)BN*SS];
__device__ float g_h     [(size_t)BN*DD];
__device__ float g_coeffs[(size_t)BN*4*DD];
__device__ float g_q     [(size_t)BN*4*DD];
__device__ float g_k     [(size_t)BN*4*DD];
__device__ float g_v     [(size_t)BN*4*DD];
__device__ float g_qn2   [BB*4*DD];
__device__ float g_kn2   [BB*4*DD];
__device__ float g_sc    [(size_t)BB*4*DD*DD];   // 64 x 512 x 512
__device__ float g_attn  [(size_t)BN*4*DD];
__device__ float g_rec   [(size_t)BN*DD];
__device__ float g_o     [(size_t)BN*DD];
__device__ float g_x1    [(size_t)BN*DD];
__device__ float g_y     [(size_t)BN*DFF];
__device__ float g_z     [(size_t)BN*DD];
__device__ float g_hf    [(size_t)BN*DD];
__device__ float g_dec   [(size_t)BN*PP];

// ---------------------------------------------------------------------------
// Helpers
// ---------------------------------------------------------------------------
__device__ __forceinline__ uint32_t f2tf(float x) {
    uint32_t r;
    asm("cvt.rna.tf32.f32 %0, %1;" : "=r"(r) : "f"(x));
    return r;
}

#define MMA8(cc, A0, A1, A2, A3, B0, B1)                                     \
    asm volatile("mma.sync.aligned.m16n8k8.row.col.f32.tf32.tf32.f32 "      \
        "{%0,%1,%2,%3}, {%4,%5,%6,%7}, {%8,%9}, {%0,%1,%2,%3};"             \
        : "+f"(cc[0]), "+f"(cc[1]), "+f"(cc[2]), "+f"(cc[3])                \
        : "r"(A0), "r"(A1), "r"(A2), "r"(A3), "r"(B0), "r"(B1))

__device__ __forceinline__ float blk_sum(float v, float* sh) {
    #pragma unroll
    for (int o = 16; o; o >>= 1) v += __shfl_xor_sync(0xffffffffu, v, o);
    int t = threadIdx.x;
    if ((t & 31) == 0) sh[t >> 5] = v;
    __syncthreads();
    v = sh[0] + sh[1] + sh[2] + sh[3] + sh[4] + sh[5] + sh[6] + sh[7];
    __syncthreads();
    return v;
}
__device__ __forceinline__ float blk_max(float v, float* sh) {
    #pragma unroll
    for (int o = 16; o; o >>= 1) v = fmaxf(v, __shfl_xor_sync(0xffffffffu, v, o));
    int t = threadIdx.x;
    if ((t & 31) == 0) sh[t >> 5] = v;
    __syncthreads();
    v = fmaxf(fmaxf(fmaxf(sh[0], sh[1]), fmaxf(sh[2], sh[3])),
              fmaxf(fmaxf(sh[4], sh[5]), fmaxf(sh[6], sh[7])));
    __syncthreads();
    return v;
}

// ---------------------------------------------------------------------------
// TF32 tensor-core GEMM tile: 128x128 CTA, BK=16, 8 warps (2x4), warp 64x32.
// Smem stored k-permuted: col = (k&3)*4 + (k>>2), row pad to 20 words, so each
// fragment load is one LDS.128 covering both k8 chunks.
// LAYOUT 0 (NT): C[m,n] = sum_k A[m*lda+k] * B[n*ldb+k]   (K % 16 == 0)
// LAYOUT 1 (TN): C[m,n] = sum_k A[k*lda+m] * B[k*ldb+n]   (arbitrary K)
// EPI 0: +bias    EPI 1: +bias, exact GELU    EPI 2: geometric wedge score
// ---------------------------------------------------------------------------
template<int LAYOUT, int EPI>
__device__ __forceinline__ void mma_tile(
    const float* __restrict__ A, const float* __restrict__ Bm,
    const float* __restrict__ bias, float* __restrict__ C,
    int M, int N, int K, int lda, int ldb, int ldc,
    const float* __restrict__ rown, const float* __restrict__ coln)
{
    constexpr int BKP = 20;
    __shared__ uint32_t As[2][128 * BKP];
    __shared__ uint32_t Bs[2][128 * BKP];

    const int tid  = threadIdx.x;
    const int lane = tid & 31;
    const int g    = lane >> 2;
    const int t    = lane & 3;
    const int wid  = tid >> 5;
    const int wm   = (wid >> 2) * 64;
    const int wn   = (wid & 3) * 32;
    const int m0   = blockIdx.y * 128;
    const int n0   = blockIdx.x * 128;

    float c[4][4][4];
    #pragma unroll
    for (int i = 0; i < 4; i++)
        #pragma unroll
        for (int j = 0; j < 4; j++)
            #pragma unroll
            for (int r = 0; r < 4; r++) c[i][j][r] = 0.f;

    // loader indices
    const int r_nt  = tid >> 1;          // 0..127
    const int kg_nt = (tid & 1) * 8;     // 0 or 8
    const int kr_tn = tid >> 4;          // 0..15
    const int mc_tn = (tid & 15) * 8;    // 0..120

    float va[8], vb[8];

    #define FETCH(k0)                                                         \
        {                                                                     \
            _Pragma("unroll")                                                 \
            for (int j = 0; j < 8; j++) { va[j] = 0.f; vb[j] = 0.f; }         \
            if (LAYOUT == 0) {                                                \
                if (m0 + r_nt < M) {                                          \
                    const float4* p = (const float4*)(A + (size_t)(m0 + r_nt) * lda + (k0) + kg_nt); \
                    float4 x0 = p[0], x1 = p[1];                              \
                    va[0]=x0.x; va[1]=x0.y; va[2]=x0.z; va[3]=x0.w;           \
                    va[4]=x1.x; va[5]=x1.y; va[6]=x1.z; va[7]=x1.w;           \
                }                                                             \
                if (n0 + r_nt < N) {                                          \
                    const float4* p = (const float4*)(Bm + (size_t)(n0 + r_nt) * ldb + (k0) + kg_nt); \
                    float4 x0 = p[0], x1 = p[1];                              \
                    vb[0]=x0.x; vb[1]=x0.y; vb[2]=x0.z; vb[3]=x0.w;           \
                    vb[4]=x1.x; vb[5]=x1.y; vb[6]=x1.z; vb[7]=x1.w;           \
                }                                                             \
            } else {                                                          \
                const int gk = (k0) + kr_tn;                                  \
                if (gk < K) {                                                 \
                    const float4* pa = (const float4*)(A + (size_t)gk * lda + m0 + mc_tn); \
                    float4 x0 = pa[0], x1 = pa[1];                            \
                    va[0]=x0.x; va[1]=x0.y; va[2]=x0.z; va[3]=x0.w;           \
                    va[4]=x1.x; va[5]=x1.y; va[6]=x1.z; va[7]=x1.w;           \
                    const float4* pb = (const float4*)(Bm + (size_t)gk * ldb + n0 + mc_tn); \
                    float4 y0 = pb[0], y1 = pb[1];                            \
                    vb[0]=y0.x; vb[1]=y0.y; vb[2]=y0.z; vb[3]=y0.w;           \
                    vb[4]=y1.x; vb[5]=y1.y; vb[6]=y1.z; vb[7]=y1.w;           \
                }                                                             \
            }                                                                 \
        }

    #define STAGE(bf)                                                        \
        {                                                                     \
            if (LAYOUT == 0) {                                                \
                _Pragma("unroll")                                             \
                for (int j = 0; j < 8; j++) {                                 \
                    const int k = kg_nt + j;                                  \
                    const int col = (k & 3) * 4 + (k >> 2);                   \
                    As[bf][r_nt * BKP + col] = f2tf(va[j]);                   \
                    Bs[bf][r_nt * BKP + col] = f2tf(vb[j]);                   \
                }                                                             \
            } else {                                                          \
                const int p = (kr_tn & 3) * 4 + (kr_tn >> 2);                 \
                _Pragma("unroll")                                             \
                for (int j = 0; j < 8; j++) {                                 \
                    As[bf][(mc_tn + j) * BKP + p] = f2tf(va[j]);              \
                    Bs[bf][(mc_tn + j) * BKP + p] = f2tf(vb[j]);              \
                }                                                             \
            }                                                                 \
        }

    #define COMPUTE(bf)                                                      \
        {                                                                     \
            uint32_t bfr[4][4];                                               \
            _Pragma("unroll")                                                 \
            for (int j = 0; j < 4; j++)                                       \
                *(uint4*)bfr[j] = *(const uint4*)&Bs[bf][(wn + j * 8 + g) * BKP + 4 * t]; \
            _Pragma("unroll")                                                 \
            for (int i = 0; i < 4; i++) {                                     \
                uint32_t a0[4], a1[4];                                        \
                *(uint4*)a0 = *(const uint4*)&As[bf][(wm + i * 16 + g)     * BKP + 4 * t]; \
                *(uint4*)a1 = *(const uint4*)&As[bf][(wm + i * 16 + 8 + g) * BKP + 4 * t]; \
                _Pragma("unroll")                                             \
                for (int j = 0; j < 4; j++) {                                 \
                    MMA8(c[i][j], a0[0], a1[0], a0[1], a1[1], bfr[j][0], bfr[j][1]); \
                    MMA8(c[i][j], a0[2], a1[2], a0[3], a1[3], bfr[j][2], bfr[j][3]); \
                }                                                             \
            }                                                                 \
        }

    const int Kt = (LAYOUT == 0) ? K : ((K + 15) & ~15);
    FETCH(0); STAGE(0); __syncthreads();
    int buf = 0;
    for (int k0 = 16; k0 < Kt; k0 += 16) {
        FETCH(k0);
        COMPUTE(buf);
        STAGE(buf ^ 1);
        __syncthreads();
        buf ^= 1;
    }
    COMPUTE(buf);

    #undef FETCH
    #undef STAGE
    #undef COMPUTE

    // Epilogue
    const float scale = rsqrtf(321.0f);
    #pragma unroll
    for (int i = 0; i < 4; i++) {
        #pragma unroll
        for (int h = 0; h < 2; h++) {
            const int gm = m0 + wm + i * 16 + g + h * 8;
            if (gm >= M) continue;
            const float rn = (EPI == 2) ? rown[gm] : 0.f;
            #pragma unroll
            for (int j = 0; j < 4; j++) {
                const int gn = n0 + wn + j * 8 + 2 * t;
                float v0 = c[i][j][h * 2 + 0];
                float v1 = c[i][j][h * 2 + 1];
                if (EPI <= 1 && bias) {
                    if (gn     < N) v0 += bias[gn];
                    if (gn + 1 < N) v1 += bias[gn + 1];
                }
                if (EPI == 1) {
                    v0 = 0.5f * v0 * (1.f + erff(v0 * 0.70710678118654752f));
                    v1 = 0.5f * v1 * (1.f + erff(v1 * 0.70710678118654752f));
                }
                if (EPI == 2) {
                    float cn0 = (gn     < N) ? coln[gn]     : 0.f;
                    float cn1 = (gn + 1 < N) ? coln[gn + 1] : 0.f;
                    float w0 = sqrtf(fmaxf(rn * cn0 - v0 * v0, 0.f) + 1e-8f);
                    float w1 = sqrtf(fmaxf(rn * cn1 - v1 * v1, 0.f) + 1e-8f);
                    v0 = (0.7f * v0 + 0.3f * w0) * scale;
                    v1 = (0.7f * v1 + 0.3f * w1) * scale;
                }
                float* p = C + (size_t)gm * ldc + gn;
                if (gn + 1 < N)      *(float2*)p = make_float2(v0, v1);
                else if (gn < N)     *p = v0;
            }
        }
    }
}

__global__ void __launch_bounds__(256) k_mma(
    const float* __restrict__ A, const float* __restrict__ B,
    const float* __restrict__ bias, float* __restrict__ C, int M, int N, int K)
{
    mma_tile<0, 0>(A, B, bias, C, M, N, K, K, K, N, nullptr, nullptr);
}
__global__ void __launch_bounds__(256) k_mma_gelu(
    const float* __restrict__ A, const float* __restrict__ B,
    const float* __restrict__ bias, float* __restrict__ C, int M, int N, int K)
{
    mma_tile<0, 1>(A, B, bias, C, M, N, K, K, K, N, nullptr, nullptr);
}

// Fused Q/K/V projection (blockIdx.z selects the projection)
__global__ void __launch_bounds__(256) k_qkv(
    const float* __restrict__ coeffs,
    const float* __restrict__ Wq, const float* __restrict__ Wk, const float* __restrict__ Wv,
    const float* __restrict__ bq, const float* __restrict__ bk, const float* __restrict__ bv,
    float* __restrict__ q, float* __restrict__ k, float* __restrict__ v)
{
    const float* W; const float* bi; float* out;
    if (blockIdx.z == 0)      { W = Wq; bi = bq; out = q; }
    else if (blockIdx.z == 1) { W = Wk; bi = bk; out = k; }
    else                      { W = Wv; bi = bv; out = v; }
    mma_tile<0, 0>(coeffs, W, bi, out, BN * 4, DD, DD, DD, DD, DD, nullptr, nullptr);
}

// dot + geometric score, batched over z = b*4 + head (TN over channels)
__global__ void __launch_bounds__(256) k_dot_geom(
    const float* __restrict__ q, const float* __restrict__ k,
    const float* __restrict__ qn2, const float* __restrict__ kn2,
    float* __restrict__ sc)
{
    const int z = blockIdx.z;
    const int b = z >> 2, m = z & 3;
    const float* A  = q + (size_t)b * NCH * 2048 + m * 512;
    const float* Bm = k + (size_t)b * NCH * 2048 + m * 512;
    float* C = sc + (size_t)z * DD * DD;
    mma_tile<1, 2>(A, Bm, nullptr, C, DD, DD, NCH, 2048, 2048, DD,
                   qn2 + z * DD, kn2 + z * DD);
}

// attn out: C[d, l] = sum_s V[d,s] * P[l,s], batched over z = b*4 + head
__global__ void __launch_bounds__(256) k_av(
    const float* __restrict__ v, const float* __restrict__ pr,
    float* __restrict__ attn)
{
    const int z = blockIdx.z;
    const int b = z >> 2, m = z & 3;
    const float* A  = v  + (size_t)b * NCH * 2048 + m * 512;
    const float* Bm = pr + (size_t)z * DD * DD;
    float* C = attn + (size_t)b * NCH * 2048 + m * 512;
    mma_tile<0, 0>(A, Bm, nullptr, C, NCH, DD, DD, 2048, DD, 2048, nullptr, nullptr);
}

// ---------------------------------------------------------------------------
// Input stats: means/stdev over S per (b, n)
// ---------------------------------------------------------------------------
__global__ void k_stats(const float* __restrict__ x,
                        float* __restrict__ means, float* __restrict__ stdev)
{
    const int b = blockIdx.x;
    const int n = blockIdx.y * 32 + threadIdx.x;
    float s = 0.f, s2 = 0.f;
    if (n < NCH) {
        for (int t = threadIdx.y; t < SS; t += 8) {
            float vv = x[((size_t)b * SS + t) * NCH + n];
            s += vv; s2 = fmaf(vv, vv, s2);
        }
    }
    __shared__ float sh[8][32], sh2[8][32];
    sh [threadIdx.y][threadIdx.x] = s;
    sh2[threadIdx.y][threadIdx.x] = s2;
    __syncthreads();
    if (threadIdx.y == 0 && n < NCH) {
        float a = 0.f, a2 = 0.f;
        #pragma unroll
        for (int i = 0; i < 8; i++) { a += sh[i][threadIdx.x]; a2 += sh2[i][threadIdx.x]; }
        float mu  = a * (1.f / SS);
        float var = a2 * (1.f / SS) - mu * mu;
        means[b * NCH + n] = mu;
        stdev[b * NCH + n] = sqrtf(var + 1e-5f);
    }
}

// Normalize + transpose: xn[b, n, s] = (x[b, s, n] - mu) / sd
__global__ void k_normT(const float* __restrict__ x,
                        const float* __restrict__ means, const float* __restrict__ stdev,
                        float* __restrict__ xn)
{
    __shared__ float tile[32][33];
    const int b  = blockIdx.z;
    const int s0 = blockIdx.x * 32;
    const int n0 = blockIdx.y * 32;
    #pragma unroll
    for (int r = 0; r < 4; r++) {
        int ss = s0 + threadIdx.y + r * 8;
        int nn = n0 + threadIdx.x;
        tile[threadIdx.y + r * 8][threadIdx.x] =
            (nn < NCH) ? x[((size_t)b * SS + ss) * NCH + nn] : 0.f;
    }
    __syncthreads();
    #pragma unroll
    for (int r = 0; r < 4; r++) {
        int nn = n0 + threadIdx.y + r * 8;
        int ss = s0 + threadIdx.x;
        if (nn < NCH) {
            float mu = means[b * NCH + nn];
            float sd = stdev[b * NCH + nn];
            xn[((size_t)b * NCH + nn) * SS + ss] =
                (tile[threadIdx.x][threadIdx.y + r * 8] - mu) / sd;
        }
    }
}

// ---------------------------------------------------------------------------
// SWT decomposition / reconstruction
// ---------------------------------------------------------------------------
__global__ void __launch_bounds__(512) k_swt_dec(
    const float* __restrict__ h, const float* __restrict__ h0,
    const float* __restrict__ h1, float* __restrict__ coeffs)
{
    const int bn = blockIdx.x;
    const int n  = bn % NCH;
    const int d  = threadIdx.x;
    __shared__ float buf[2][DD];
    buf[0][d] = h[(size_t)bn * DD + d];
    float f0[3], f1[3];
    #pragma unroll
    for (int kk = 0; kk < 3; kk++) { f0[kk] = h0[n * 3 + kk]; f1[kk] = h1[n * 3 + kk]; }
    __syncthreads();
    int cur = 0, dil = 1;
    const int pl[3] = {1, 1, 2};
    #pragma unroll
    for (int m = 0; m < 3; m++) {
        float det = 0.f, app = 0.f;
        #pragma unroll
        for (int kk = 0; kk < 3; kk++) {
            int idx = (d + kk * dil - pl[m] + DD) & (DD - 1);
            float vv = buf[cur][idx];
            det = fmaf(f1[kk], vv, det);
            app = fmaf(f0[kk], vv, app);
        }
        coeffs[((size_t)bn * 4 + (3 - m)) * DD + d] = det;
        buf[cur ^ 1][d] = app;
        __syncthreads();
        cur ^= 1; dil <<= 1;
    }
    coeffs[(size_t)bn * 4 * DD + d] = buf[cur][d];
}

__global__ void __launch_bounds__(512) k_swt_rec(
    const float* __restrict__ c, const float* __restrict__ g0,
    const float* __restrict__ g1, float* __restrict__ rec)
{
    const int bn = blockIdx.x;
    const int n  = bn % NCH;
    const int d  = threadIdx.x;
    __shared__ float app[2][DD];
    __shared__ float det[DD];
    app[0][d] = c[(size_t)bn * 4 * DD + d];
    float f0[3], f1[3];
    #pragma unroll
    for (int kk = 0; kk < 3; kk++) { f0[kk] = g0[n * 3 + kk]; f1[kk] = g1[n * 3 + kk]; }
    int cur = 0, dil = 4;
    const int pl[3] = {6, 3, 1};
    #pragma unroll
    for (int i = 0; i < 3; i++) {
        det[d] = c[((size_t)bn * 4 + 1 + i) * DD + d];
        __syncthreads();
        float acc = 0.f;
        #pragma unroll
        for (int kk = 0; kk < 3; kk++) {
            int idx = (d + kk * dil - pl[i] + DD) & (DD - 1);
            acc = fmaf(f0[kk], app[cur][idx], acc);
            acc = fmaf(f1[kk], det[idx], acc);
        }
        app[cur ^ 1][d] = 0.5f * acc;
        __syncthreads();
        cur ^= 1; dil >>= 1;
    }
    rec[(size_t)bn * DD + d] = app[cur][d];
}

// Row norms of Q and K over channels, per (b, head, l)
__global__ void __launch_bounds__(256) k_qknorms(
    const float* __restrict__ q, const float* __restrict__ k,
    float* __restrict__ qn2, float* __restrict__ kn2)
{
    const int z = blockIdx.y;
    const int b = z >> 2, m = z & 3;
    const int l = blockIdx.x * 256 + threadIdx.x;
    const size_t base = (size_t)b * NCH * 2048 + m * 512 + l;
    float sq = 0.f, sk = 0.f;
    for (int j = 0; j < NCH; j++) {
        float a = q[base + (size_t)j * 2048]; sq = fmaf(a, a, sq);
        float c = k[base + (size_t)j * 2048]; sk = fmaf(c, c, sk);
    }
    qn2[z * DD + l] = sq;
    kn2[z * DD + l] = sk;
}

// Softmax over 512 columns, one row per block
__global__ void __launch_bounds__(256) k_softmax512(float* __restrict__ sc)
{
    float* row = sc + (size_t)blockIdx.x * DD;
    const int t = threadIdx.x;
    __shared__ float sh[8];
    float v0 = row[t], v1 = row[t + 256];
    float mx = blk_max(fmaxf(v0, v1), sh);
    float e0 = expf(v0 - mx), e1 = expf(v1 - mx);
    float s = blk_sum(e0 + e1, sh);
    float inv = 1.f / s;
    row[t]       = e0 * inv;
    row[t + 256] = e1 * inv;
}

// LayerNorm over D=512 (optionally fused residual add)
__global__ void __launch_bounds__(256) k_ln(
    const float* __restrict__ x, const float* __restrict__ res,
    const float* __restrict__ g, const float* __restrict__ bt,
    float* __restrict__ out)
{
    const size_t base = (size_t)blockIdx.x * DD;
    const int t = threadIdx.x;
    __shared__ float sh[8];
    float v0 = x[base + t], v1 = x[base + t + 256];
    if (res) { v0 += res[base + t]; v1 += res[base + t + 256]; }
    float s = blk_sum(v0 + v1, sh);
    float mu = s * (1.f / DD);
    float d0 = v0 - mu, d1 = v1 - mu;
    float vs = blk_sum(d0 * d0 + d1 * d1, sh);
    float rs = rsqrtf(vs * (1.f / DD) + 1e-5f);
    out[base + t]       = d0 * rs * g[t]       + bt[t];
    out[base + t + 256] = d1 * rs * g[t + 256] + bt[t + 256];
}

// dec output: out[b, p, n] = dec[b, n, p] * stdev[b, n] + means[b, n]
__global__ void k_dec_out(const float* __restrict__ dec,
                          const float* __restrict__ means, const float* __restrict__ stdev,
                          float* __restrict__ out)
{
    const int idx = blockIdx.x * 256 + threadIdx.x;
    if (idx >= BB * PP * NCH) return;
    const int n = idx % NCH;
    const int p = (idx / NCH) % PP;
    const int b = idx / (NCH * PP);
    out[idx] = dec[((size_t)b * NCH + n) * PP + p] * stdev[b * NCH + n] + means[b * NCH + n];
}

__global__ void k_tail(const float* __restrict__ means, const float* __restrict__ stdev,
                       float* __restrict__ out)
{
    const int i = blockIdx.x * 256 + threadIdx.x;
    if (i < BN) { out[i] = means[i]; out[BN + i] = stdev[i]; }
}

// ---------------------------------------------------------------------------
// Launch
// ---------------------------------------------------------------------------
extern "C" void kernel_launch(void* const* d_in, const int* in_sizes, int n_in,
                              void* d_out, int out_size)
{
    const float* x_enc  = (const float*)d_in[0];
    const float* emb_W  = (const float*)d_in[1];
    const float* emb_b  = (const float*)d_in[2];
    const float* h0     = (const float*)d_in[3];
    const float* h1     = (const float*)d_in[4];
    const float* g0     = (const float*)d_in[5];
    const float* g1     = (const float*)d_in[6];
    const float* Wq     = (const float*)d_in[7];
    const float* bq     = (const float*)d_in[8];
    const float* Wk     = (const float*)d_in[9];
    const float* bk     = (const float*)d_in[10];
    const float* Wv     = (const float*)d_in[11];
    const float* bv     = (const float*)d_in[12];
    const float* Wo     = (const float*)d_in[13];
    const float* bo     = (const float*)d_in[14];
    const float* W1     = (const float*)d_in[15];
    const float* b1     = (const float*)d_in[16];
    const float* W2     = (const float*)d_in[17];
    const float* b2     = (const float*)d_in[18];
    const float* ln1_g  = (const float*)d_in[19];
    const float* ln1_b  = (const float*)d_in[20];
    const float* ln2_g  = (const float*)d_in[21];
    const float* ln2_b  = (const float*)d_in[22];
    const float* lnf_g  = (const float*)d_in[23];
    const float* lnf_b  = (const float*)d_in[24];
    const float* proj_W = (const float*)d_in[25];
    const float* proj_b = (const float*)d_in[26];

    float *means, *stdev, *xn, *h, *coeffs, *q, *k, *v, *qn2, *kn2, *sc,
          *attn, *rec, *o, *x1, *y, *z, *hf, *dec;
    cudaGetSymbolAddress((void**)&means,  g_means);
    cudaGetSymbolAddress((void**)&stdev,  g_stdev);
    cudaGetSymbolAddress((void**)&xn,     g_xn);
    cudaGetSymbolAddress((void**)&h,      g_h);
    cudaGetSymbolAddress((void**)&coeffs, g_coeffs);
    cudaGetSymbolAddress((void**)&q,      g_q);
    cudaGetSymbolAddress((void**)&k,      g_k);
    cudaGetSymbolAddress((void**)&v,      g_v);
    cudaGetSymbolAddress((void**)&qn2,    g_qn2);
    cudaGetSymbolAddress((void**)&kn2,    g_kn2);
    cudaGetSymbolAddress((void**)&sc,     g_sc);
    cudaGetSymbolAddress((void**)&attn,   g_attn);
    cudaGetSymbolAddress((void**)&rec,    g_rec);
    cudaGetSymbolAddress((void**)&o,      g_o);
    cudaGetSymbolAddress((void**)&x1,     g_x1);
    cudaGetSymbolAddress((void**)&y,      g_y);
    cudaGetSymbolAddress((void**)&z,      g_z);
    cudaGetSymbolAddress((void**)&hf,     g_hf);
    cudaGetSymbolAddress((void**)&dec,    g_dec);

    // Input stats + normalized transpose
    k_stats<<<dim3(BB, (NCH + 31) / 32), dim3(32, 8)>>>(x_enc, means, stdev);
    k_normT<<<dim3(SS / 32, (NCH + 31) / 32, BB), dim3(32, 8)>>>(x_enc, means, stdev, xn);

    // Embedding: h[bn, d] = xn[bn, :] . emb_W[d, :]
    k_mma<<<dim3(DD / 128, (BN + 127) / 128), 256>>>(xn, emb_W, emb_b, h, BN, DD, SS);

    const dim3 gQKV(DD / 128, (BN * 4 + 127) / 128, 3);
    const dim3 gD  (DD / 128, (BN + 127) / 128);

    for (int l = 0; l < 2; l++) {
        const float* h0l = h0 + (size_t)l * NCH * 3;
        const float* h1l = h1 + (size_t)l * NCH * 3;
        const float* g0l = g0 + (size_t)l * NCH * 3;
        const float* g1l = g1 + (size_t)l * NCH * 3;

        k_swt_dec<<<BN, DD>>>(h, h0l, h1l, coeffs);

        k_qkv<<<gQKV, 256>>>(coeffs,
                             Wq + (size_t)l * DD * DD, Wk + (size_t)l * DD * DD,
                             Wv + (size_t)l * DD * DD,
                             bq + l * DD, bk + l * DD, bv + l * DD, q, k, v);

        k_qknorms<<<dim3(2, BB * 4), 256>>>(q, k, qn2, kn2);
        k_dot_geom<<<dim3(4, 4, BB * 4), 256>>>(q, k, qn2, kn2, sc);
        k_softmax512<<<BB * 4 * DD, 256>>>(sc);
        k_av<<<dim3(4, (NCH + 127) / 128, BB * 4), 256>>>(v, sc, attn);

        k_swt_rec<<<BN, DD>>>(attn, g0l, g1l, rec);

        k_mma<<<gD, 256>>>(rec, Wo + (size_t)l * DD * DD, bo + l * DD, o, BN, DD, DD);
        k_ln<<<BN, 256>>>(h, o, ln1_g + l * DD, ln1_b + l * DD, x1);

        k_mma_gelu<<<dim3(DFF / 128, (BN + 127) / 128), 256>>>(
            x1, W1 + (size_t)l * DFF * DD, b1 + l * DFF, y, BN, DFF, DD);
        k_mma<<<gD, 256>>>(y, W2 + (size_t)l * DD * DFF, b2 + l * DD, z, BN, DD, DFF);
        k_ln<<<BN, 256>>>(x1, z, ln2_g + l * DD, ln2_b + l * DD, h);
    }

    // Final LN + projection + de-normalization
    k_ln<<<BN, 256>>>(h, nullptr, lnf_g, lnf_b, hf);
    k_mma<<<dim3((PP + 127) / 128, (BN + 127) / 128), 256>>>(hf, proj_W, proj_b, dec, BN, PP, DD);
    k_dec_out<<<(BB * PP * NCH + 255) / 256, 256>>>(dec, means, stdev, (float*)d_out);

    // Tuple tail: (dec, means, stdev) flattened
    if (out_size >= BB * PP * NCH + 2 * BN)
        k_tail<<<(BN + 255) / 256, 256>>>(means, stdev, (float*)d_out + BB * PP * NCH);
}